// round 10
// baseline (speedup 1.0000x reference)
#include <cuda_runtime.h>
#include <cuda_bf16.h>

#define NMAX 100000
#define EMAX 1600000
#define SCAN_B 256

// Scratch (device globals; no allocation allowed).
__device__ float4 g_h1[NMAX * 16];    // N x 64  (x@W1) ; later decoder hidden
__device__ float4 g_h2[NMAX * 8];     // N x 32  (z1@W2 via fused GEMV)
__device__ int    g_cnt[NMAX];
__device__ float  g_dinv[NMAX];
__device__ int    g_src[EMAX];
__device__ int    g_dst[EMAX];
__device__ int    g_rowptr[NMAX + 1];
__device__ int    g_cursor[NMAX];
__device__ int2   g_csr[EMAX];        // (src, norm-bits), grouped by dst
__device__ int    g_is64;
__device__ int    g_bsum[512];
__device__ int    g_arrive1;
__device__ int    g_arrive2;

// ---------------------------------------------------------------------------
// f32x2 packed-FMA helpers (Blackwell FFMA2).
__device__ __forceinline__ unsigned long long pack2(float x) {
    unsigned long long r;
    asm("mov.b64 %0, {%1, %1};" : "=l"(r) : "f"(x));
    return r;
}
__device__ __forceinline__ void fma2(unsigned long long& d, unsigned long long a,
                                     unsigned long long b) {
    asm("fma.rn.f32x2 %0, %1, %2, %0;" : "+l"(d) : "l"(a), "l"(b));
}
__device__ __forceinline__ float2 unpack2(unsigned long long v) {
    float2 r;
    asm("mov.b64 {%0, %1}, %2;" : "=f"(r.x), "=f"(r.y) : "l"(v));
    return r;
}

// ---------------------------------------------------------------------------
// Zero counts + barrier counters + detect edge dtype.
__global__ void init_kernel(const int* __restrict__ ei_raw, int n) {
    int i = blockIdx.x * blockDim.x + threadIdx.x;
    if (i < n) g_cnt[i] = 0;
    if (i == 0) {
        g_arrive1 = 0;
        g_arrive2 = 0;
        int all_zero = 1;
        for (int k = 1; k < 256; k += 2)
            if (ei_raw[k] != 0) { all_zero = 0; break; }
        g_is64 = all_zero;
    }
}

// Convert indices -> int32 (clamped), histogram in-degree.
__global__ void prep_idx_kernel(const void* __restrict__ ei_raw, int e, int n) {
    int i = blockIdx.x * blockDim.x + threadIdx.x;
    if (i >= e) return;
    int s, d;
    if (g_is64) {
        const long long* p = (const long long*)ei_raw;
        s = (int)p[i];
        d = (int)p[e + i];
    } else {
        const int* p = (const int*)ei_raw;
        s = p[i];
        d = p[e + i];
    }
    s = min(max(s, 0), n - 1);
    d = min(max(d, 0), n - 1);
    g_src[i] = s;
    g_dst[i] = d;
    atomicAdd(&g_cnt[d], 1);
}

__device__ __forceinline__ void grid_spin_barrier(int* ctr, int nblk, int t) {
    if (t == 0) {
        __threadfence();
        atomicAdd(ctr, 1);
        while (*(volatile int*)ctr < nblk) { }
        __threadfence();
    }
    __syncthreads();
}

// Fused scan + scatter: local scan -> spin barrier -> prefix -> write
// rowptr/cursor/dinv -> spin barrier -> grid-stride atomic scatter.
// All 391 blocks co-resident (391 << capacity) so spin barriers are safe.
__global__ void scan_scatter_kernel(int n, int e, int nblk) {
    __shared__ int s[SCAN_B];
    int t = threadIdx.x;
    int bid = blockIdx.x;
    int gid = bid * SCAN_B + t;
    int c = (gid < n) ? g_cnt[gid] : 0;
    s[t] = c;
    __syncthreads();
    for (int off = 1; off < SCAN_B; off <<= 1) {
        int add = (t >= off) ? s[t - off] : 0;
        __syncthreads();
        s[t] += add;
        __syncthreads();
    }
    int incl = s[t];
    int total = s[SCAN_B - 1];
    if (t == 0) g_bsum[bid] = total;
    grid_spin_barrier(&g_arrive1, nblk, t);

    int pre = 0;
    for (int i = t; i < bid; i += SCAN_B) pre += g_bsum[i];
    __syncthreads();
    s[t] = pre;
    __syncthreads();
    for (int off = SCAN_B / 2; off > 0; off >>= 1) {
        if (t < off) s[t] += s[t + off];
        __syncthreads();
    }
    int ex = s[0] + incl - c;
    if (gid < n) {
        g_rowptr[gid] = ex;
        g_cursor[gid] = ex;
        g_dinv[gid]   = rsqrtf((float)c + 1.0f);
        if (gid == n - 1) g_rowptr[n] = ex + c;
    }
    grid_spin_barrier(&g_arrive2, nblk, t);

    // Scatter phase (grid-stride over edges).
    int stride = nblk * SCAN_B;
    for (int i = bid * SCAN_B + t; i < e; i += stride) {
        int ss = g_src[i], d = g_dst[i];
        int pos = atomicAdd(&g_cursor[d], 1);
        float nrm = g_dinv[ss] * g_dinv[d];
        g_csr[pos] = make_int2(ss, __float_as_int(nrm));
    }
}

// ---------------------------------------------------------------------------
// Layer 1 fused: warp-per-node pull over h1 (64-dim, float2/lane, 8-edge
// unroll), relu epilogue, then in-warp GEMV (64x32, W2 in smem) -> h2.
__global__ void layer1_kernel(const float2* __restrict__ h, float* __restrict__ h2out,
                              const float2* __restrict__ bias,
                              const float* __restrict__ W2, int n) {
    __shared__ float W2s[64 * 32];
    int tid = threadIdx.x;
    for (int i = tid; i < 64 * 32 / 4; i += 256)
        reinterpret_cast<float4*>(W2s)[i] = reinterpret_cast<const float4*>(W2)[i];
    __syncthreads();

    int gw = (blockIdx.x * blockDim.x + tid) >> 5;
    int lane = tid & 31;
    if (gw >= n) return;
    int beg = g_rowptr[gw];
    int end = g_rowptr[gw + 1];
    float2 acc = make_float2(0.f, 0.f);
    int j = beg;
    for (; j + 8 <= end; j += 8) {
        int2 m[8];
        float2 v[8];
#pragma unroll
        for (int q = 0; q < 8; q++) m[q] = g_csr[j + q];
#pragma unroll
        for (int q = 0; q < 8; q++) v[q] = h[(size_t)m[q].x * 32 + lane];
#pragma unroll
        for (int q = 0; q < 8; q++) {
            float nm = __int_as_float(m[q].y);
            acc.x = fmaf(v[q].x, nm, acc.x);
            acc.y = fmaf(v[q].y, nm, acc.y);
        }
    }
    for (; j < end; j++) {
        int2 m = g_csr[j];
        float2 v = h[(size_t)m.x * 32 + lane];
        float nm = __int_as_float(m.y);
        acc.x = fmaf(v.x, nm, acc.x); acc.y = fmaf(v.y, nm, acc.y);
    }
    float di = g_dinv[gw];
    float sl = di * di;
    float2 hv = h[(size_t)gw * 32 + lane];
    float2 b = bias[lane];
    acc.x = fmaxf(acc.x + hv.x * sl + b.x, 0.f);
    acc.y = fmaxf(acc.y + hv.y * sl + b.y, 0.f);

    // GEMV: h2[c=lane] = sum_k z1[k] * W2[k][c]
    float hacc = 0.f;
#pragma unroll
    for (int k = 0; k < 32; k++) {
        float ax = __shfl_sync(0xffffffffu, acc.x, k);
        float ay = __shfl_sync(0xffffffffu, acc.y, k);
        hacc = fmaf(ax, W2s[(2 * k) * 32 + lane], hacc);
        hacc = fmaf(ay, W2s[(2 * k + 1) * 32 + lane], hacc);
    }
    h2out[(size_t)gw * 32 + lane] = hacc;
}

// ---------------------------------------------------------------------------
// Layer 2 + decoder-hidden fused: warp-per-node pull over h2 (32-dim, 8-edge
// unroll), + self + b2 -> z_out, then in-warp GEMV (32x64, Wd1) + bd1 + relu.
__global__ void layer2_kernel(const float* __restrict__ h, float* __restrict__ z_out,
                              const float* __restrict__ b2,
                              const float* __restrict__ Wd1,
                              const float* __restrict__ bd1,
                              float2* __restrict__ hidden, int n) {
    __shared__ float Wd1s[32 * 64];
    __shared__ float bd1s[64];
    int tid = threadIdx.x;
    for (int i = tid; i < 32 * 64 / 4; i += 256)
        reinterpret_cast<float4*>(Wd1s)[i] = reinterpret_cast<const float4*>(Wd1)[i];
    if (tid < 16)
        reinterpret_cast<float4*>(bd1s)[tid] = reinterpret_cast<const float4*>(bd1)[tid];
    __syncthreads();

    int gw = (blockIdx.x * blockDim.x + tid) >> 5;
    int lane = tid & 31;
    if (gw >= n) return;
    int beg = g_rowptr[gw];
    int end = g_rowptr[gw + 1];
    float acc = 0.f;
    int j = beg;
    for (; j + 8 <= end; j += 8) {
        int2 m[8];
        float v[8];
#pragma unroll
        for (int q = 0; q < 8; q++) m[q] = g_csr[j + q];
#pragma unroll
        for (int q = 0; q < 8; q++) v[q] = h[(size_t)m[q].x * 32 + lane];
#pragma unroll
        for (int q = 0; q < 8; q++)
            acc = fmaf(v[q], __int_as_float(m[q].y), acc);
    }
    for (; j < end; j++) {
        int2 m = g_csr[j];
        acc = fmaf(h[(size_t)m.x * 32 + lane], __int_as_float(m.y), acc);
    }
    float di = g_dinv[gw];
    acc += h[(size_t)gw * 32 + lane] * di * di + b2[lane];
    z_out[(size_t)gw * 32 + lane] = acc;

    // GEMV: hidden[2lane,2lane+1] = relu(sum_k z[k]*Wd1[k][:] + bd1)
    const float2* Wd1s2 = reinterpret_cast<const float2*>(Wd1s);
    const float2* bd1s2 = reinterpret_cast<const float2*>(bd1s);
    float2 hacc = bd1s2[lane];
#pragma unroll
    for (int k = 0; k < 32; k++) {
        float zk = __shfl_sync(0xffffffffu, acc, k);
        float2 w = Wd1s2[k * 32 + lane];
        hacc.x = fmaf(zk, w.x, hacc.x);
        hacc.y = fmaf(zk, w.y, hacc.y);
    }
    hacc.x = fmaxf(hacc.x, 0.f);
    hacc.y = fmaxf(hacc.y, 0.f);
    hidden[(size_t)gw * 32 + lane] = hacc;
}

// ---------------------------------------------------------------------------
// Register-blocked GEMM, f32x2 packed FMAs, KC=32 K-chunks.
template <int KI, int KO, int RPB, bool BIAS, bool RELU>
__global__ void __launch_bounds__(256)
gemm_kernel(const float* __restrict__ in, const float* __restrict__ W,
            const float* __restrict__ bias, float* __restrict__ out, int n) {
    constexpr int TPC = KO / 4;
    constexpr int RT  = 256 / TPC;
    constexpr int R   = RPB / RT;
    static_assert(R >= 1 && R <= 4, "bad tile");
    constexpr int KC  = (KI < 32) ? KI : 32;
    constexpr int XP  = KC + 4;

    __shared__ float ws[KC * KO];
    __shared__ float xs[RPB * XP];

    int tid = threadIdx.x;
    int row0 = blockIdx.x * RPB;
    int ctid = tid % TPC;
    int rtid = tid / TPC;
    int r0 = rtid * R;

    unsigned long long acc[R][2];
#pragma unroll
    for (int i = 0; i < R; i++) { acc[i][0] = 0ull; acc[i][1] = 0ull; }

    for (int kc0 = 0; kc0 < KI; kc0 += KC) {
        for (int i = tid; i < KC * KO / 4; i += 256)
            reinterpret_cast<float4*>(ws)[i] =
                reinterpret_cast<const float4*>(W + (size_t)kc0 * KO)[i];
        for (int i = tid; i < RPB * KC / 4; i += 256) {
            int row = i / (KC / 4);
            int c4 = i % (KC / 4);
            int g = row0 + row;
            float4 v = make_float4(0.f, 0.f, 0.f, 0.f);
            if (g < n)
                v = reinterpret_cast<const float4*>(in)[(size_t)g * (KI / 4) + kc0 / 4 + c4];
            *reinterpret_cast<float4*>(&xs[row * XP + c4 * 4]) = v;
        }
        __syncthreads();

#pragma unroll
        for (int k4 = 0; k4 < KC / 4; k4++) {
            float4 xv[R];
#pragma unroll
            for (int i = 0; i < R; i++)
                xv[i] = *reinterpret_cast<const float4*>(&xs[(r0 + i) * XP + k4 * 4]);
#pragma unroll
            for (int kk = 0; kk < 4; kk++) {
                ulonglong2 w = *reinterpret_cast<const ulonglong2*>(
                    &ws[(k4 * 4 + kk) * KO + ctid * 4]);
#pragma unroll
                for (int i = 0; i < R; i++) {
                    float xsc = reinterpret_cast<const float*>(&xv[i])[kk];
                    unsigned long long xx = pack2(xsc);
                    fma2(acc[i][0], xx, w.x);
                    fma2(acc[i][1], xx, w.y);
                }
            }
        }
        __syncthreads();
    }

    float4 bv = make_float4(0.f, 0.f, 0.f, 0.f);
    if (BIAS) bv = *reinterpret_cast<const float4*>(&bias[ctid * 4]);
#pragma unroll
    for (int i = 0; i < R; i++) {
        int g = row0 + r0 + i;
        if (g >= n) continue;
        float2 lo = unpack2(acc[i][0]);
        float2 hi = unpack2(acc[i][1]);
        float4 o = make_float4(lo.x + bv.x, lo.y + bv.y, hi.x + bv.z, hi.y + bv.w);
        if (RELU) {
            o.x = fmaxf(o.x, 0.f); o.y = fmaxf(o.y, 0.f);
            o.z = fmaxf(o.z, 0.f); o.w = fmaxf(o.w, 0.f);
        }
        *reinterpret_cast<float4*>(&out[(size_t)g * KO + ctid * 4]) = o;
    }
}

// ---------------------------------------------------------------------------
extern "C" void kernel_launch(void* const* d_in, const int* in_sizes, int n_in,
                              void* d_out, int out_size) {
    const float* x   = (const float*)d_in[0];
    const void*  ei  = d_in[1];
    const float* W1  = (const float*)d_in[2];
    const float* b1  = (const float*)d_in[3];
    const float* W2  = (const float*)d_in[4];
    const float* b2  = (const float*)d_in[5];
    const float* Wd1 = (const float*)d_in[6];
    const float* bd1 = (const float*)d_in[7];
    const float* Wd2 = (const float*)d_in[8];
    const float* bd2 = (const float*)d_in[9];

    int n = in_sizes[0] / 128;   // 100000
    int e = in_sizes[1] / 2;     // 1600000

    float* rec_out = (float*)d_out;                 // [N,128]
    float* z_out   = rec_out + (long long)n * 128;  // [N,32]

    void *p_h1, *p_h2;
    cudaGetSymbolAddress(&p_h1, g_h1);
    cudaGetSymbolAddress(&p_h2, g_h2);
    float* h1 = (float*)p_h1;
    float* h2 = (float*)p_h2;

    const int B = 256;
    int warp_blocks = (n * 32 + B - 1) / B;
    int nblk = (n + SCAN_B - 1) / SCAN_B;   // 391

    init_kernel<<<(n + B - 1) / B, B>>>((const int*)ei, n);                 // 0
    prep_idx_kernel<<<(e + B - 1) / B, B>>>(ei, e, n);                      // 1
    scan_scatter_kernel<<<nblk, SCAN_B>>>(n, e, nblk);                      // 2
    gemm_kernel<128, 64, 64, false, false><<<(n + 63) / 64, B>>>(x, W1, nullptr, h1, n); // 3 (profiled)
    layer1_kernel<<<warp_blocks, B>>>((const float2*)h1, h2,
                                      (const float2*)b1, W2, n);            // 4
    layer2_kernel<<<warp_blocks, B>>>(h2, z_out, b2, Wd1, bd1,
                                      (float2*)h1, n);                      // 5
    gemm_kernel<64, 128, 32, true, false><<<(n + 31) / 32, B>>>(h1, Wd2, bd2, rec_out, n); // 6
}

// round 12
// speedup vs baseline: 1.0145x; 1.0145x over previous
#include <cuda_runtime.h>
#include <cuda_bf16.h>

#define NMAX 100000
#define EMAX 1600000
#define SCAN_B 256

// Scratch (device globals; no allocation allowed).
__device__ float4 g_h1[NMAX * 16];    // N x 64  (x@W1) ; later decoder hidden
__device__ float4 g_h2[NMAX * 8];     // N x 32  (z1@W2 via fused GEMV)
__device__ int    g_cnt[NMAX];
__device__ float  g_dinv[NMAX];
__device__ int    g_src[EMAX];
__device__ int    g_dst[EMAX];
__device__ int    g_rowptr[NMAX + 1];
__device__ int    g_cursor[NMAX];
__device__ int2   g_csr[EMAX];        // (src, norm-bits), grouped by dst
__device__ int    g_bsum[512];
__device__ int    g_arrive[2];

// ---------------------------------------------------------------------------
// f32x2 packed-FMA helpers (Blackwell FFMA2).
__device__ __forceinline__ unsigned long long pack2(float x) {
    unsigned long long r;
    asm("mov.b64 %0, {%1, %1};" : "=l"(r) : "f"(x));
    return r;
}
__device__ __forceinline__ void fma2(unsigned long long& d, unsigned long long a,
                                     unsigned long long b) {
    asm("fma.rn.f32x2 %0, %1, %2, %0;" : "+l"(d) : "l"(a), "l"(b));
}
__device__ __forceinline__ float2 unpack2(unsigned long long v) {
    float2 r;
    asm("mov.b64 {%0, %1}, %2;" : "=f"(r.x), "=f"(r.y) : "l"(v));
    return r;
}

// ---------------------------------------------------------------------------
// Convert indices -> int32 (clamped), histogram in-degree.
// Edge dtype detected block-locally: for int64 (LE) all odd 32-bit words of
// small non-negative values are zero; for int32 they're random node ids.
__global__ void prep_idx_kernel(const int* __restrict__ ei_raw, int e, int n) {
    int tid = threadIdx.x;
    int v = 0;
    if (tid < 128) v = ei_raw[2 * tid + 1];
    int is64 = __syncthreads_and(v == 0);

    int i = blockIdx.x * blockDim.x + tid;
    if (i >= e) return;
    int s, d;
    if (is64) {
        const long long* p = (const long long*)ei_raw;
        s = (int)p[i];
        d = (int)p[e + i];
    } else {
        s = ei_raw[i];
        d = ei_raw[e + i];
    }
    s = min(max(s, 0), n - 1);
    d = min(max(d, 0), n - 1);
    g_src[i] = s;
    g_dst[i] = d;
    atomicAdd(&g_cnt[d], 1);
}

__device__ __forceinline__ void grid_spin_barrier(int* ctr, int nblk, int t) {
    if (t == 0) {
        __threadfence();
        atomicAdd(ctr, 1);
        while (*(volatile int*)ctr < nblk) { }
        __threadfence();
    }
    __syncthreads();
}

// Fused scan + scatter (391 co-resident blocks; spin barriers safe).
__global__ void scan_scatter_kernel(int n, int e, int nblk) {
    __shared__ int s[SCAN_B];
    int t = threadIdx.x;
    int bid = blockIdx.x;
    int gid = bid * SCAN_B + t;
    int c = (gid < n) ? g_cnt[gid] : 0;
    s[t] = c;
    __syncthreads();
    for (int off = 1; off < SCAN_B; off <<= 1) {
        int add = (t >= off) ? s[t - off] : 0;
        __syncthreads();
        s[t] += add;
        __syncthreads();
    }
    int incl = s[t];
    int total = s[SCAN_B - 1];
    if (t == 0) g_bsum[bid] = total;
    grid_spin_barrier(&g_arrive[0], nblk, t);

    int pre = 0;
    for (int i = t; i < bid; i += SCAN_B) pre += g_bsum[i];
    __syncthreads();
    s[t] = pre;
    __syncthreads();
    for (int off = SCAN_B / 2; off > 0; off >>= 1) {
        if (t < off) s[t] += s[t + off];
        __syncthreads();
    }
    int ex = s[0] + incl - c;
    if (gid < n) {
        g_rowptr[gid] = ex;
        g_cursor[gid] = ex;
        g_dinv[gid]   = rsqrtf((float)c + 1.0f);
        if (gid == n - 1) g_rowptr[n] = ex + c;
    }
    grid_spin_barrier(&g_arrive[1], nblk, t);

    int stride = nblk * SCAN_B;
    for (int i = bid * SCAN_B + t; i < e; i += stride) {
        int ss = g_src[i], d = g_dst[i];
        int pos = atomicAdd(&g_cursor[d], 1);
        float nrm = g_dinv[ss] * g_dinv[d];
        g_csr[pos] = make_int2(ss, __float_as_int(nrm));
    }
}

// ---------------------------------------------------------------------------
// Layer 1 fused: warp-per-node pull over h1 (64-dim). float4 per lane,
// 16 lanes per edge -> half-warps process 2 edges concurrently; xor-reduce;
// then in-warp GEMV (64x32, W2 in smem) -> h2. z1 never materialized.
__global__ void layer1_kernel(const float4* __restrict__ h4, float* __restrict__ h2out,
                              const float4* __restrict__ b1_4,
                              const float* __restrict__ W2, int n) {
    __shared__ float W2s[64 * 32];
    int tid = threadIdx.x;
    for (int i = tid; i < 64 * 32 / 4; i += 256)
        reinterpret_cast<float4*>(W2s)[i] = reinterpret_cast<const float4*>(W2)[i];
    __syncthreads();

    int gw = (blockIdx.x * blockDim.x + tid) >> 5;
    int lane = tid & 31;
    if (gw >= n) return;
    int half = lane >> 4;        // 0/1: which edge of the pair
    int hl   = lane & 15;        // column block (hl*4 .. hl*4+3)
    int beg = g_rowptr[gw];
    int end = g_rowptr[gw + 1];

    float4 acc = make_float4(0.f, 0.f, 0.f, 0.f);
    int j = beg + half;          // this half's edges: stride 2
    for (; j + 6 < end; j += 8) {
        int2 m[4];
        float4 v[4];
#pragma unroll
        for (int q = 0; q < 4; q++) m[q] = g_csr[j + 2 * q];
#pragma unroll
        for (int q = 0; q < 4; q++) v[q] = h4[(size_t)m[q].x * 16 + hl];
#pragma unroll
        for (int q = 0; q < 4; q++) {
            float nm = __int_as_float(m[q].y);
            acc.x = fmaf(v[q].x, nm, acc.x);
            acc.y = fmaf(v[q].y, nm, acc.y);
            acc.z = fmaf(v[q].z, nm, acc.z);
            acc.w = fmaf(v[q].w, nm, acc.w);
        }
    }
    for (; j < end; j += 2) {
        int2 m = g_csr[j];
        float4 v = h4[(size_t)m.x * 16 + hl];
        float nm = __int_as_float(m.y);
        acc.x = fmaf(v.x, nm, acc.x);
        acc.y = fmaf(v.y, nm, acc.y);
        acc.z = fmaf(v.z, nm, acc.z);
        acc.w = fmaf(v.w, nm, acc.w);
    }
    // Combine the two half-warp partial sums (both halves end with full sum).
    acc.x += __shfl_xor_sync(0xffffffffu, acc.x, 16);
    acc.y += __shfl_xor_sync(0xffffffffu, acc.y, 16);
    acc.z += __shfl_xor_sync(0xffffffffu, acc.z, 16);
    acc.w += __shfl_xor_sync(0xffffffffu, acc.w, 16);

    float di = g_dinv[gw];
    float sl = di * di;
    float4 hv = h4[(size_t)gw * 16 + hl];
    float4 b = b1_4[hl];
    acc.x = fmaxf(fmaf(hv.x, sl, acc.x) + b.x, 0.f);
    acc.y = fmaxf(fmaf(hv.y, sl, acc.y) + b.y, 0.f);
    acc.z = fmaxf(fmaf(hv.z, sl, acc.z) + b.z, 0.f);
    acc.w = fmaxf(fmaf(hv.w, sl, acc.w) + b.w, 0.f);

    // GEMV: h2[c=lane] = sum_k z1[k]*W2[k][c];  z1[4*k16+cc] = comp cc @ lane k16.
    float hacc = 0.f;
#pragma unroll
    for (int k16 = 0; k16 < 16; k16++) {
        float zx = __shfl_sync(0xffffffffu, acc.x, k16);
        float zy = __shfl_sync(0xffffffffu, acc.y, k16);
        float zz = __shfl_sync(0xffffffffu, acc.z, k16);
        float zw = __shfl_sync(0xffffffffu, acc.w, k16);
        hacc = fmaf(zx, W2s[(4 * k16 + 0) * 32 + lane], hacc);
        hacc = fmaf(zy, W2s[(4 * k16 + 1) * 32 + lane], hacc);
        hacc = fmaf(zz, W2s[(4 * k16 + 2) * 32 + lane], hacc);
        hacc = fmaf(zw, W2s[(4 * k16 + 3) * 32 + lane], hacc);
    }
    h2out[(size_t)gw * 32 + lane] = hacc;
}

// ---------------------------------------------------------------------------
// Layer 2 + decoder hidden fused: pull over h2 (32-dim). float4 per lane,
// 8 lanes per edge -> 4 edges concurrently; xor-reduce; z -> z_out;
// in-warp GEMV (32x64, Wd1) + bd1 + relu -> hidden.
__global__ void layer2_kernel(const float4* __restrict__ h4, float4* __restrict__ z_out4,
                              const float4* __restrict__ b2_4,
                              const float* __restrict__ Wd1,
                              const float* __restrict__ bd1,
                              float2* __restrict__ hidden, int n) {
    __shared__ float Wd1s[32 * 64];
    __shared__ float bd1s[64];
    int tid = threadIdx.x;
    for (int i = tid; i < 32 * 64 / 4; i += 256)
        reinterpret_cast<float4*>(Wd1s)[i] = reinterpret_cast<const float4*>(Wd1)[i];
    if (tid < 16)
        reinterpret_cast<float4*>(bd1s)[tid] = reinterpret_cast<const float4*>(bd1)[tid];
    __syncthreads();

    int gw = (blockIdx.x * blockDim.x + tid) >> 5;
    int lane = tid & 31;
    if (gw >= n) return;
    int q  = lane >> 3;          // 0..3: which edge of the quad
    int ql = lane & 7;           // column block (ql*4 .. ql*4+3)
    int beg = g_rowptr[gw];
    int end = g_rowptr[gw + 1];

    float4 acc = make_float4(0.f, 0.f, 0.f, 0.f);
    int j = beg + q;             // this quarter's edges: stride 4
    for (; j + 12 < end; j += 16) {
        int2 m[4];
        float4 v[4];
#pragma unroll
        for (int p = 0; p < 4; p++) m[p] = g_csr[j + 4 * p];
#pragma unroll
        for (int p = 0; p < 4; p++) v[p] = h4[(size_t)m[p].x * 8 + ql];
#pragma unroll
        for (int p = 0; p < 4; p++) {
            float nm = __int_as_float(m[p].y);
            acc.x = fmaf(v[p].x, nm, acc.x);
            acc.y = fmaf(v[p].y, nm, acc.y);
            acc.z = fmaf(v[p].z, nm, acc.z);
            acc.w = fmaf(v[p].w, nm, acc.w);
        }
    }
    for (; j < end; j += 4) {
        int2 m = g_csr[j];
        float4 v = h4[(size_t)m.x * 8 + ql];
        float nm = __int_as_float(m.y);
        acc.x = fmaf(v.x, nm, acc.x);
        acc.y = fmaf(v.y, nm, acc.y);
        acc.z = fmaf(v.z, nm, acc.z);
        acc.w = fmaf(v.w, nm, acc.w);
    }
    // Reduce the 4 quarter partials.
    acc.x += __shfl_xor_sync(0xffffffffu, acc.x, 8);
    acc.y += __shfl_xor_sync(0xffffffffu, acc.y, 8);
    acc.z += __shfl_xor_sync(0xffffffffu, acc.z, 8);
    acc.w += __shfl_xor_sync(0xffffffffu, acc.w, 8);
    acc.x += __shfl_xor_sync(0xffffffffu, acc.x, 16);
    acc.y += __shfl_xor_sync(0xffffffffu, acc.y, 16);
    acc.z += __shfl_xor_sync(0xffffffffu, acc.z, 16);
    acc.w += __shfl_xor_sync(0xffffffffu, acc.w, 16);

    float di = g_dinv[gw];
    float sl = di * di;
    float4 hv = h4[(size_t)gw * 8 + ql];
    float4 b = b2_4[ql];
    acc.x = fmaf(hv.x, sl, acc.x) + b.x;
    acc.y = fmaf(hv.y, sl, acc.y) + b.y;
    acc.z = fmaf(hv.z, sl, acc.z) + b.z;
    acc.w = fmaf(hv.w, sl, acc.w) + b.w;

    if (lane < 8) z_out4[(size_t)gw * 8 + lane] = acc;

    // GEMV: hidden[2lane,2lane+1] = relu(sum_k z[k]*Wd1[k][:] + bd1).
    // z[4*k8+cc] = comp cc @ lane k8 (k8 = 0..7).
    const float2* Wd1s2 = reinterpret_cast<const float2*>(Wd1s);
    const float2* bd1s2 = reinterpret_cast<const float2*>(bd1s);
    float2 hacc = bd1s2[lane];
#pragma unroll
    for (int k8 = 0; k8 < 8; k8++) {
        float zx = __shfl_sync(0xffffffffu, acc.x, k8);
        float zy = __shfl_sync(0xffffffffu, acc.y, k8);
        float zz = __shfl_sync(0xffffffffu, acc.z, k8);
        float zw = __shfl_sync(0xffffffffu, acc.w, k8);
        float2 w0 = Wd1s2[(4 * k8 + 0) * 32 + lane];
        float2 w1 = Wd1s2[(4 * k8 + 1) * 32 + lane];
        float2 w2 = Wd1s2[(4 * k8 + 2) * 32 + lane];
        float2 w3 = Wd1s2[(4 * k8 + 3) * 32 + lane];
        hacc.x = fmaf(zx, w0.x, hacc.x); hacc.y = fmaf(zx, w0.y, hacc.y);
        hacc.x = fmaf(zy, w1.x, hacc.x); hacc.y = fmaf(zy, w1.y, hacc.y);
        hacc.x = fmaf(zz, w2.x, hacc.x); hacc.y = fmaf(zz, w2.y, hacc.y);
        hacc.x = fmaf(zw, w3.x, hacc.x); hacc.y = fmaf(zw, w3.y, hacc.y);
    }
    hacc.x = fmaxf(hacc.x, 0.f);
    hacc.y = fmaxf(hacc.y, 0.f);
    hidden[(size_t)gw * 32 + lane] = hacc;
}

// ---------------------------------------------------------------------------
// Register-blocked GEMM, f32x2 packed FMAs, KC=32 K-chunks.
template <int KI, int KO, int RPB, bool BIAS, bool RELU>
__global__ void __launch_bounds__(256)
gemm_kernel(const float* __restrict__ in, const float* __restrict__ W,
            const float* __restrict__ bias, float* __restrict__ out, int n) {
    constexpr int TPC = KO / 4;
    constexpr int RT  = 256 / TPC;
    constexpr int R   = RPB / RT;
    static_assert(R >= 1 && R <= 4, "bad tile");
    constexpr int KC  = (KI < 32) ? KI : 32;
    constexpr int XP  = KC + 4;

    __shared__ float ws[KC * KO];
    __shared__ float xs[RPB * XP];

    int tid = threadIdx.x;
    int row0 = blockIdx.x * RPB;
    int ctid = tid % TPC;
    int rtid = tid / TPC;
    int r0 = rtid * R;

    unsigned long long acc[R][2];
#pragma unroll
    for (int i = 0; i < R; i++) { acc[i][0] = 0ull; acc[i][1] = 0ull; }

    for (int kc0 = 0; kc0 < KI; kc0 += KC) {
        for (int i = tid; i < KC * KO / 4; i += 256)
            reinterpret_cast<float4*>(ws)[i] =
                reinterpret_cast<const float4*>(W + (size_t)kc0 * KO)[i];
        for (int i = tid; i < RPB * KC / 4; i += 256) {
            int row = i / (KC / 4);
            int c4 = i % (KC / 4);
            int g = row0 + row;
            float4 v = make_float4(0.f, 0.f, 0.f, 0.f);
            if (g < n)
                v = reinterpret_cast<const float4*>(in)[(size_t)g * (KI / 4) + kc0 / 4 + c4];
            *reinterpret_cast<float4*>(&xs[row * XP + c4 * 4]) = v;
        }
        __syncthreads();

#pragma unroll
        for (int k4 = 0; k4 < KC / 4; k4++) {
            float4 xv[R];
#pragma unroll
            for (int i = 0; i < R; i++)
                xv[i] = *reinterpret_cast<const float4*>(&xs[(r0 + i) * XP + k4 * 4]);
#pragma unroll
            for (int kk = 0; kk < 4; kk++) {
                ulonglong2 w = *reinterpret_cast<const ulonglong2*>(
                    &ws[(k4 * 4 + kk) * KO + ctid * 4]);
#pragma unroll
                for (int i = 0; i < R; i++) {
                    float xsc = reinterpret_cast<const float*>(&xv[i])[kk];
                    unsigned long long xx = pack2(xsc);
                    fma2(acc[i][0], xx, w.x);
                    fma2(acc[i][1], xx, w.y);
                }
            }
        }
        __syncthreads();
    }

    float4 bv = make_float4(0.f, 0.f, 0.f, 0.f);
    if (BIAS) bv = *reinterpret_cast<const float4*>(&bias[ctid * 4]);
#pragma unroll
    for (int i = 0; i < R; i++) {
        int g = row0 + r0 + i;
        if (g >= n) continue;
        float2 lo = unpack2(acc[i][0]);
        float2 hi = unpack2(acc[i][1]);
        float4 o = make_float4(lo.x + bv.x, lo.y + bv.y, hi.x + bv.z, hi.y + bv.w);
        if (RELU) {
            o.x = fmaxf(o.x, 0.f); o.y = fmaxf(o.y, 0.f);
            o.z = fmaxf(o.z, 0.f); o.w = fmaxf(o.w, 0.f);
        }
        *reinterpret_cast<float4*>(&out[(size_t)g * KO + ctid * 4]) = o;
    }
}

// ---------------------------------------------------------------------------
extern "C" void kernel_launch(void* const* d_in, const int* in_sizes, int n_in,
                              void* d_out, int out_size) {
    const float* x   = (const float*)d_in[0];
    const void*  ei  = d_in[1];
    const float* W1  = (const float*)d_in[2];
    const float* b1  = (const float*)d_in[3];
    const float* W2  = (const float*)d_in[4];
    const float* b2  = (const float*)d_in[5];
    const float* Wd1 = (const float*)d_in[6];
    const float* bd1 = (const float*)d_in[7];
    const float* Wd2 = (const float*)d_in[8];
    const float* bd2 = (const float*)d_in[9];

    int n = in_sizes[0] / 128;   // 100000
    int e = in_sizes[1] / 2;     // 1600000

    float* rec_out = (float*)d_out;                 // [N,128]
    float* z_out   = rec_out + (long long)n * 128;  // [N,32]

    void *p_h1, *p_h2, *p_cnt, *p_arr;
    cudaGetSymbolAddress(&p_h1, g_h1);
    cudaGetSymbolAddress(&p_h2, g_h2);
    cudaGetSymbolAddress(&p_cnt, g_cnt);
    cudaGetSymbolAddress(&p_arr, g_arrive);
    float* h1 = (float*)p_h1;
    float* h2 = (float*)p_h2;

    const int B = 256;
    int warp_blocks = (n * 32 + B - 1) / B;
    int nblk = (n + SCAN_B - 1) / SCAN_B;   // 391

    // Zero counters via memset nodes (not kernel launches).
    cudaMemsetAsync(p_cnt, 0, (size_t)n * sizeof(int));
    cudaMemsetAsync(p_arr, 0, 2 * sizeof(int));

    prep_idx_kernel<<<(e + B - 1) / B, B>>>((const int*)ei, e, n);          // k0
    scan_scatter_kernel<<<nblk, SCAN_B>>>(n, e, nblk);                      // k1
    gemm_kernel<128, 64, 64, false, false><<<(n + 63) / 64, B>>>(x, W1, nullptr, h1, n); // k2
    layer1_kernel<<<warp_blocks, B>>>((const float4*)h1, h2,
                                      (const float4*)b1, W2, n);            // k3 (profiled)
    layer2_kernel<<<warp_blocks, B>>>((const float4*)h2, (float4*)z_out,
                                      (const float4*)b2, Wd1, bd1,
                                      (float2*)h1, n);                      // k4
    gemm_kernel<64, 128, 32, true, false><<<(n + 31) / 32, B>>>(h1, Wd2, bd2, rec_out, n); // k5
}